// round 2
// baseline (speedup 1.0000x reference)
#include <cuda_runtime.h>
#include <math.h>

// ---------------- problem constants ----------------
#define D_   1024
#define H_   8
#define E_   128
#define B_   4
#define S_   2048
#define NT_  (B_ * S_)         // 8192 tokens
#define EPS_ 1e-6f

// ---------------- GEMM tiling ----------------
#define BM 128
#define BN 128
#define BK 16

// ---------------- attention tiling ----------------
#define QT 64
#define KT 64
#define QKV_STRIDE 132          // 128 + 4 pad (keeps float4 alignment)
#define P_STRIDE   68
#define ATTN_SMEM  ((3 * KT * QKV_STRIDE + KT * P_STRIDE) * 4)

// ---------------- device scratch ----------------
__device__ float g_mod [NT_ * D_];
__device__ float g_h   [NT_ * D_];
__device__ float g_q   [NT_ * D_];
__device__ float g_k   [NT_ * D_];
__device__ float g_v   [NT_ * D_];
__device__ float g_mod2[NT_ * D_];
__device__ float g_h2  [NT_ * D_];

__device__ __forceinline__ float elu1(float x) { return x > 0.f ? x : expm1f(x); }

// ============================================================
// Generic 128x128x16 fp32 GEMM core, 256 threads, 8x8 micro-tile
// A: [*, lda] row-major (tile origin already applied)
// Bm: [K, ldb] row-major (tile col origin already applied)
// ============================================================
template <bool FFN>
__device__ __forceinline__ void gemm_core(const float* __restrict__ A, int lda,
                                          const float* __restrict__ Bm, int ldb,
                                          float* __restrict__ C, int ldc, int K,
                                          const float* __restrict__ bias,
                                          const float* __restrict__ resid) {
  __shared__ float As[BK][BM + 4];   // stored transposed: As[k][m]
  __shared__ float Bs[BK][BN];
  const int t = threadIdx.x;
  const int tr = t >> 4, tc = t & 15;
  const int arow = t >> 2;           // 0..63
  const int acol = (t & 3) << 2;     // 0,4,8,12
  const int brow = t >> 5;           // 0..7
  const int bcol = (t & 31) << 2;    // 0..124

  float acc[8][8];
#pragma unroll
  for (int i = 0; i < 8; i++)
#pragma unroll
    for (int j = 0; j < 8; j++) acc[i][j] = 0.f;

  for (int k0 = 0; k0 < K; k0 += BK) {
#pragma unroll
    for (int i = 0; i < 2; i++) {
      int r = arow + i * 64;
      float4 v = *(const float4*)(A + (size_t)r * lda + k0 + acol);
      As[acol + 0][r] = v.x;
      As[acol + 1][r] = v.y;
      As[acol + 2][r] = v.z;
      As[acol + 3][r] = v.w;
    }
#pragma unroll
    for (int i = 0; i < 2; i++) {
      int r = brow + i * 8;
      *(float4*)&Bs[r][bcol] = *(const float4*)(Bm + (size_t)(k0 + r) * ldb + bcol);
    }
    __syncthreads();
#pragma unroll
    for (int kk = 0; kk < BK; kk++) {
      float ra[8], rb[8];
      *(float4*)(ra)     = *(const float4*)&As[kk][tr * 8];
      *(float4*)(ra + 4) = *(const float4*)&As[kk][tr * 8 + 4];
      *(float4*)(rb)     = *(const float4*)&Bs[kk][tc * 8];
      *(float4*)(rb + 4) = *(const float4*)&Bs[kk][tc * 8 + 4];
#pragma unroll
      for (int i = 0; i < 8; i++)
#pragma unroll
        for (int j = 0; j < 8; j++) acc[i][j] = fmaf(ra[i], rb[j], acc[i][j]);
    }
    __syncthreads();
  }

#pragma unroll
  for (int i = 0; i < 8; i++) {
    int r = tr * 8 + i;
#pragma unroll
    for (int j = 0; j < 8; j += 4) {
      int cx = tc * 8 + j;
      float4 o;
      o.x = acc[i][j]; o.y = acc[i][j + 1]; o.z = acc[i][j + 2]; o.w = acc[i][j + 3];
      if (FFN) {
        float4 rv = *(const float4*)(resid + (size_t)r * ldc + cx);
        o.x = rv.x + elu1(o.x + bias[cx]);
        o.y = rv.y + elu1(o.y + bias[cx + 1]);
        o.z = rv.z + elu1(o.z + bias[cx + 2]);
        o.w = rv.w + elu1(o.w + bias[cx + 3]);
      }
      *(float4*)(C + (size_t)r * ldc + cx) = o;
    }
  }
}

// mod = x @ W_in
__global__ void __launch_bounds__(256, 2) k_gemm_dense(const float* __restrict__ A,
                                                       const float* __restrict__ W,
                                                       float* __restrict__ C) {
  const size_t moff = (size_t)blockIdx.y * BM * D_;
  gemm_core<false>(A + moff, D_, W + blockIdx.x * BN, D_,
                   C + moff + blockIdx.x * BN, D_, D_, nullptr, nullptr);
}

// out = resid + elu(A @ W + bias)
__global__ void __launch_bounds__(256, 2) k_gemm_ffn(const float* __restrict__ A,
                                                     const float* __restrict__ W,
                                                     const float* __restrict__ bias,
                                                     const float* __restrict__ resid,
                                                     float* __restrict__ C) {
  const size_t moff = (size_t)blockIdx.y * BM * D_;
  const size_t off = moff + blockIdx.x * BN;
  gemm_core<true>(A + moff, D_, W + blockIdx.x * BN, D_, C + off, D_, D_,
                  bias + blockIdx.x * BN, resid + off);
}

// per-head projection: Out[b,h,s,:] = h_slice[b,s,h*128:(h+1)*128] @ W[h]
__global__ void __launch_bounds__(256, 2) k_gemm_head(const float* __restrict__ Hm,
                                                      const float* __restrict__ W,
                                                      float* __restrict__ Out) {
  const int bh = blockIdx.z;
  const int b = bh >> 3, h = bh & 7;
  const float* A = Hm + ((size_t)b * S_ + (size_t)blockIdx.y * BM) * D_ + h * E_;
  const float* Wp = W + h * E_ * E_;
  float* C = Out + ((size_t)bh * S_ + (size_t)blockIdx.y * BM) * E_;
  gemm_core<false>(A, D_, Wp, E_, C, E_, E_, nullptr, nullptr);
}

// ============================================================
// LayerNorm over last dim (1024), one block per row
// ============================================================
__global__ void __launch_bounds__(256) k_ln(const float* __restrict__ in,
                                            float* __restrict__ out,
                                            const float* __restrict__ gamma,
                                            const float* __restrict__ beta) {
  const size_t row = blockIdx.x;
  const int t = threadIdx.x;
  float4 v = ((const float4*)(in + row * D_))[t];
  float s  = v.x + v.y + v.z + v.w;
  float s2 = v.x * v.x + v.y * v.y + v.z * v.z + v.w * v.w;
#pragma unroll
  for (int off = 16; off; off >>= 1) {
    s  += __shfl_xor_sync(0xffffffffu, s, off);
    s2 += __shfl_xor_sync(0xffffffffu, s2, off);
  }
  __shared__ float sb[16];
  if ((t & 31) == 0) { sb[t >> 5] = s; sb[(t >> 5) + 8] = s2; }
  __syncthreads();
  float tot = 0.f, tot2 = 0.f;
#pragma unroll
  for (int i = 0; i < 8; i++) { tot += sb[i]; tot2 += sb[i + 8]; }
  const float mean = tot * (1.f / D_);
  const float var  = tot2 * (1.f / D_) - mean * mean;
  const float inv  = rsqrtf(var + EPS_);
  float4 g  = ((const float4*)gamma)[t];
  float4 bb = ((const float4*)beta)[t];
  float4 o;
  o.x = (v.x - mean) * inv * g.x + bb.x;
  o.y = (v.y - mean) * inv * g.y + bb.y;
  o.z = (v.z - mean) * inv * g.z + bb.z;
  o.w = (v.w - mean) * inv * g.w + bb.w;
  ((float4*)(out + row * D_))[t] = o;
}

// ============================================================
// Flash-style attention (unscaled scores), fused residual:
//   modout[b,s,h*128+e] = modin[...] + softmax(q k^T) v
// Block: (q-tile=64, head, batch), 256 threads.
// Thread (tr = t/16, tc = t%16):
//   scores: rows 4tr..4tr+3, cols {tc, 16+tc, 32+tc, 48+tc}
//   output: rows 4tr..4tr+3, cols tc*8..tc*8+7
// ============================================================
__global__ void __launch_bounds__(256) k_attn(const float* __restrict__ Qg,
                                              const float* __restrict__ Kg,
                                              const float* __restrict__ Vg,
                                              const float* __restrict__ modin,
                                              float* __restrict__ modout) {
  extern __shared__ float sm[];
  float* q_s = sm;
  float* k_s = sm + KT * QKV_STRIDE;
  float* v_s = sm + 2 * KT * QKV_STRIDE;
  float* p_s = sm + 3 * KT * QKV_STRIDE;   // [kc][row], stride P_STRIDE

  const int t = threadIdx.x;
  const int tr = t >> 4, tc = t & 15;
  const int q0 = blockIdx.x * QT;
  const int h = blockIdx.y, b = blockIdx.z;
  const size_t bh = (size_t)b * H_ + h;

  {
    const float* Qp = Qg + (bh * S_ + q0) * E_;
    const int row = t >> 5, col = (t & 31) << 2;
#pragma unroll
    for (int i = 0; i < 8; i++) {
      int r = row + i * 8;
      *(float4*)&q_s[r * QKV_STRIDE + col] = *(const float4*)(Qp + (size_t)r * E_ + col);
    }
  }

  float o[4][8];
#pragma unroll
  for (int r = 0; r < 4; r++)
#pragma unroll
    for (int j = 0; j < 8; j++) o[r][j] = 0.f;
  float m[4], l[4];
#pragma unroll
  for (int r = 0; r < 4; r++) { m[r] = -1e30f; l[r] = 0.f; }

  const float* Kp = Kg + bh * S_ * E_;
  const float* Vp = Vg + bh * S_ * E_;

  for (int kt = 0; kt < S_ / KT; kt++) {
    {
      const int row = t >> 5, col = (t & 31) << 2;
      const float* kb = Kp + (size_t)kt * KT * E_;
      const float* vb = Vp + (size_t)kt * KT * E_;
#pragma unroll
      for (int i = 0; i < 8; i++) {
        int r = row + i * 8;
        *(float4*)&k_s[r * QKV_STRIDE + col] = *(const float4*)(kb + (size_t)r * E_ + col);
        *(float4*)&v_s[r * QKV_STRIDE + col] = *(const float4*)(vb + (size_t)r * E_ + col);
      }
    }
    __syncthreads();

    // ---- phase A: scores 64x64 = Q K^T ----
    float sc[4][4];
#pragma unroll
    for (int r = 0; r < 4; r++)
#pragma unroll
      for (int c = 0; c < 4; c++) sc[r][c] = 0.f;
#pragma unroll 4
    for (int kk = 0; kk < E_; kk += 4) {
      float4 qv[4], kv[4];
#pragma unroll
      for (int r = 0; r < 4; r++)
        qv[r] = *(const float4*)&q_s[(4 * tr + r) * QKV_STRIDE + kk];
#pragma unroll
      for (int c = 0; c < 4; c++)
        kv[c] = *(const float4*)&k_s[(16 * c + tc) * QKV_STRIDE + kk];
#pragma unroll
      for (int r = 0; r < 4; r++)
#pragma unroll
        for (int c = 0; c < 4; c++) {
          sc[r][c] = fmaf(qv[r].x, kv[c].x, sc[r][c]);
          sc[r][c] = fmaf(qv[r].y, kv[c].y, sc[r][c]);
          sc[r][c] = fmaf(qv[r].z, kv[c].z, sc[r][c]);
          sc[r][c] = fmaf(qv[r].w, kv[c].w, sc[r][c]);
        }
    }

    // ---- online softmax update (16-lane row groups) ----
#pragma unroll
    for (int r = 0; r < 4; r++) {
      float mt = fmaxf(fmaxf(sc[r][0], sc[r][1]), fmaxf(sc[r][2], sc[r][3]));
#pragma unroll
      for (int off = 8; off; off >>= 1)
        mt = fmaxf(mt, __shfl_xor_sync(0xffffffffu, mt, off));
      float mn = fmaxf(m[r], mt);
      float alpha = __expf(m[r] - mn);
      m[r] = mn;
      float pv[4];
      float rs = 0.f;
#pragma unroll
      for (int c = 0; c < 4; c++) { pv[c] = __expf(sc[r][c] - mn); rs += pv[c]; }
#pragma unroll
      for (int off = 8; off; off >>= 1)
        rs += __shfl_xor_sync(0xffffffffu, rs, off);
      l[r] = l[r] * alpha + rs;
#pragma unroll
      for (int j = 0; j < 8; j++) o[r][j] *= alpha;
#pragma unroll
      for (int c = 0; c < 4; c++)
        p_s[(16 * c + tc) * P_STRIDE + 4 * tr + r] = pv[c];
    }
    __syncthreads();

    // ---- phase B: O += P V ----
#pragma unroll 4
    for (int kc = 0; kc < KT; kc++) {
      float4 pq = *(const float4*)&p_s[kc * P_STRIDE + 4 * tr];
      float4 v0 = *(const float4*)&v_s[kc * QKV_STRIDE + tc * 8];
      float4 v1 = *(const float4*)&v_s[kc * QKV_STRIDE + tc * 8 + 4];
      float pr[4] = {pq.x, pq.y, pq.z, pq.w};
      float vv[8] = {v0.x, v0.y, v0.z, v0.w, v1.x, v1.y, v1.z, v1.w};
#pragma unroll
      for (int r = 0; r < 4; r++)
#pragma unroll
        for (int j = 0; j < 8; j++) o[r][j] = fmaf(pr[r], vv[j], o[r][j]);
    }
    __syncthreads();
  }

  // ---- epilogue: normalize + residual add ----
#pragma unroll
  for (int r = 0; r < 4; r++) {
    const float inv = 1.f / l[r];
    const int row = q0 + 4 * tr + r;
    const size_t base = ((size_t)b * S_ + row) * D_ + (size_t)h * E_ + tc * 8;
    float4 m0 = *(const float4*)(modin + base);
    float4 m1 = *(const float4*)(modin + base + 4);
    float4 o0, o1;
    o0.x = m0.x + o[r][0] * inv;
    o0.y = m0.y + o[r][1] * inv;
    o0.z = m0.z + o[r][2] * inv;
    o0.w = m0.w + o[r][3] * inv;
    o1.x = m1.x + o[r][4] * inv;
    o1.y = m1.y + o[r][5] * inv;
    o1.z = m1.z + o[r][6] * inv;
    o1.w = m1.w + o[r][7] * inv;
    *(float4*)(modout + base)     = o0;
    *(float4*)(modout + base + 4) = o1;
  }
}

// ============================================================
extern "C" void kernel_launch(void* const* d_in, const int* in_sizes, int n_in,
                              void* d_out, int out_size) {
  const float* x     = (const float*)d_in[0];
  const float* W_in  = (const float*)d_in[1];
  const float* gamma = (const float*)d_in[2];
  const float* beta  = (const float*)d_in[3];
  const float* Wq    = (const float*)d_in[4];
  const float* Wk    = (const float*)d_in[5];
  const float* Wv    = (const float*)d_in[6];
  const float* Wf    = (const float*)d_in[7];
  const float* bf    = (const float*)d_in[8];
  float* out = (float*)d_out;

  float *mod, *h, *q, *k, *v, *mod2, *h2;
  cudaGetSymbolAddress((void**)&mod,  g_mod);
  cudaGetSymbolAddress((void**)&h,    g_h);
  cudaGetSymbolAddress((void**)&q,    g_q);
  cudaGetSymbolAddress((void**)&k,    g_k);
  cudaGetSymbolAddress((void**)&v,    g_v);
  cudaGetSymbolAddress((void**)&mod2, g_mod2);
  cudaGetSymbolAddress((void**)&h2,   g_h2);

  cudaFuncSetAttribute(k_attn, cudaFuncAttributeMaxDynamicSharedMemorySize, ATTN_SMEM);

  dim3 gdense(D_ / BN, NT_ / BM);      // (8, 64)
  k_gemm_dense<<<gdense, 256>>>(x, W_in, mod);

  k_ln<<<NT_, 256>>>(mod, h, gamma, beta);

  dim3 ghead(1, S_ / BM, B_ * H_);     // (1, 16, 32)
  k_gemm_head<<<ghead, 256>>>(h, Wq, q);
  k_gemm_head<<<ghead, 256>>>(h, Wk, k);
  k_gemm_head<<<ghead, 256>>>(h, Wv, v);

  dim3 gattn(S_ / QT, H_, B_);         // (32, 8, 4)
  k_attn<<<gattn, 256, ATTN_SMEM>>>(q, k, v, mod, mod2);

  k_ln<<<NT_, 256>>>(mod2, h2, gamma, beta);

  k_gemm_ffn<<<gdense, 256>>>(h2, Wf, bf, mod2, out);
}

// round 3
// speedup vs baseline: 2.8715x; 2.8715x over previous
#include <cuda_runtime.h>
#include <math.h>
#include <stdint.h>

// ---------------- problem constants ----------------
#define D_   1024
#define H_   8
#define E_   128
#define B_   4
#define S_   2048
#define NT_  (B_ * S_)
#define EPS_ 1e-6f

// ---------------- device scratch ----------------
__device__ float g_mod [NT_ * D_];
__device__ float g_h   [NT_ * D_];
__device__ float g_q   [NT_ * D_];
__device__ float g_k   [NT_ * D_];
__device__ float g_v   [NT_ * D_];
__device__ float g_mod2[NT_ * D_];
__device__ float g_h2  [NT_ * D_];

__device__ __forceinline__ float elu1(float x) { return x > 0.f ? x : expm1f(x); }

__device__ __forceinline__ float f2tf(float f) {
  uint32_t u;
  asm("cvt.rna.tf32.f32 %0, %1;" : "=r"(u) : "f"(f));
  return __uint_as_float(u);
}

__device__ __forceinline__ void mma_tf32(float* d, const uint32_t* a, const uint32_t* b) {
  asm volatile(
      "mma.sync.aligned.m16n8k8.row.col.f32.tf32.tf32.f32 "
      "{%0,%1,%2,%3}, {%4,%5,%6,%7}, {%8,%9}, {%0,%1,%2,%3};"
      : "+f"(d[0]), "+f"(d[1]), "+f"(d[2]), "+f"(d[3])
      : "r"(a[0]), "r"(a[1]), "r"(a[2]), "r"(a[3]), "r"(b[0]), "r"(b[1]));
}

// ============================================================
// TF32 tensor-core GEMM: 128x128 block tile, K-tile 32.
// 256 threads = 8 warps (2 x 4), warp tile 64x32.
// ============================================================
#define GBM 128
#define GBN 128
#define GBK 32
#define LDA_S 36
#define LDB_S 136

template <bool FFN>
__device__ __forceinline__ void gemm_tf32_core(
    const float* __restrict__ A, int lda,
    const float* __restrict__ Bm, int ldb,
    float* __restrict__ C, int ldc, int K,
    const float* __restrict__ bias, const float* __restrict__ resid) {
  __shared__ float As[GBM * LDA_S];
  __shared__ float Bs[GBK * LDB_S];

  const int t = threadIdx.x;
  const int lane = t & 31, wid = t >> 5;
  const int g = lane >> 2, tg = lane & 3;
  const int wr = wid >> 2, wc = wid & 3;

  const int a_c = (t & 7) * 4;   // 0..28
  const int a_r = t >> 3;        // 0..31
  const int b_c = (t & 31) * 4;  // 0..124
  const int b_r = t >> 5;        // 0..7

  float acc[4][4][4];
#pragma unroll
  for (int i = 0; i < 4; i++)
#pragma unroll
    for (int j = 0; j < 4; j++)
#pragma unroll
      for (int r = 0; r < 4; r++) acc[i][j][r] = 0.f;

  for (int k0 = 0; k0 < K; k0 += GBK) {
#pragma unroll
    for (int i = 0; i < 4; i++) {
      int r = a_r + i * 32;
      float4 v = *(const float4*)(A + (size_t)r * lda + k0 + a_c);
      float4 w = make_float4(f2tf(v.x), f2tf(v.y), f2tf(v.z), f2tf(v.w));
      *(float4*)&As[r * LDA_S + a_c] = w;
    }
#pragma unroll
    for (int i = 0; i < 4; i++) {
      int r = b_r + i * 8;
      float4 v = *(const float4*)(Bm + (size_t)(k0 + r) * ldb + b_c);
      float4 w = make_float4(f2tf(v.x), f2tf(v.y), f2tf(v.z), f2tf(v.w));
      *(float4*)&Bs[r * LDB_S + b_c] = w;
    }
    __syncthreads();

    const uint32_t* as = (const uint32_t*)As;
    const uint32_t* bs = (const uint32_t*)Bs;
#pragma unroll
    for (int kk = 0; kk < GBK; kk += 8) {
      uint32_t af[4][4], bf[4][2];
#pragma unroll
      for (int i = 0; i < 4; i++) {
        int r0 = wr * 64 + i * 16;
        af[i][0] = as[(r0 + g) * LDA_S + kk + tg];
        af[i][1] = as[(r0 + g + 8) * LDA_S + kk + tg];
        af[i][2] = as[(r0 + g) * LDA_S + kk + tg + 4];
        af[i][3] = as[(r0 + g + 8) * LDA_S + kk + tg + 4];
      }
#pragma unroll
      for (int j = 0; j < 4; j++) {
        int c0 = wc * 32 + j * 8;
        bf[j][0] = bs[(kk + tg) * LDB_S + c0 + g];
        bf[j][1] = bs[(kk + tg + 4) * LDB_S + c0 + g];
      }
#pragma unroll
      for (int i = 0; i < 4; i++)
#pragma unroll
        for (int j = 0; j < 4; j++) mma_tf32(acc[i][j], af[i], bf[j]);
    }
    __syncthreads();
  }

  // epilogue
#pragma unroll
  for (int i = 0; i < 4; i++) {
    int rA = wr * 64 + i * 16 + g;
    int rB = rA + 8;
#pragma unroll
    for (int j = 0; j < 4; j++) {
      int c = wc * 32 + j * 8 + 2 * tg;
      float2 o0 = make_float2(acc[i][j][0], acc[i][j][1]);
      float2 o1 = make_float2(acc[i][j][2], acc[i][j][3]);
      if (FFN) {
        float2 bv = *(const float2*)(bias + c);
        float2 r0 = *(const float2*)(resid + (size_t)rA * ldc + c);
        float2 r1 = *(const float2*)(resid + (size_t)rB * ldc + c);
        o0.x = r0.x + elu1(o0.x + bv.x);
        o0.y = r0.y + elu1(o0.y + bv.y);
        o1.x = r1.x + elu1(o1.x + bv.x);
        o1.y = r1.y + elu1(o1.y + bv.y);
      }
      *(float2*)(C + (size_t)rA * ldc + c) = o0;
      *(float2*)(C + (size_t)rB * ldc + c) = o1;
    }
  }
}

__global__ void __launch_bounds__(256) k_gemm_dense(const float* __restrict__ A,
                                                    const float* __restrict__ W,
                                                    float* __restrict__ C) {
  const size_t moff = (size_t)blockIdx.y * GBM * D_;
  gemm_tf32_core<false>(A + moff, D_, W + blockIdx.x * GBN, D_,
                        C + moff + blockIdx.x * GBN, D_, D_, nullptr, nullptr);
}

__global__ void __launch_bounds__(256) k_gemm_ffn(const float* __restrict__ A,
                                                  const float* __restrict__ W,
                                                  const float* __restrict__ bias,
                                                  const float* __restrict__ resid,
                                                  float* __restrict__ C) {
  const size_t moff = (size_t)blockIdx.y * GBM * D_;
  const size_t off = moff + blockIdx.x * GBN;
  gemm_tf32_core<true>(A + moff, D_, W + blockIdx.x * GBN, D_, C + off, D_, D_,
                       bias + blockIdx.x * GBN, resid + off);
}

__global__ void __launch_bounds__(256) k_gemm_head(const float* __restrict__ Hm,
                                                   const float* __restrict__ W,
                                                   float* __restrict__ Out) {
  const int bh = blockIdx.y;
  const int b = bh >> 3, h = bh & 7;
  const float* A = Hm + ((size_t)b * S_ + (size_t)blockIdx.x * GBM) * D_ + h * E_;
  const float* Wp = W + h * E_ * E_;
  float* C = Out + ((size_t)bh * S_ + (size_t)blockIdx.x * GBM) * E_;
  gemm_tf32_core<false>(A, D_, Wp, E_, C, E_, E_, nullptr, nullptr);
}

// ============================================================
// LayerNorm over last dim (1024), one block per row
// ============================================================
__global__ void __launch_bounds__(256) k_ln(const float* __restrict__ in,
                                            float* __restrict__ out,
                                            const float* __restrict__ gamma,
                                            const float* __restrict__ beta) {
  const size_t row = blockIdx.x;
  const int t = threadIdx.x;
  float4 v = ((const float4*)(in + row * D_))[t];
  float s  = v.x + v.y + v.z + v.w;
  float s2 = v.x * v.x + v.y * v.y + v.z * v.z + v.w * v.w;
#pragma unroll
  for (int off = 16; off; off >>= 1) {
    s  += __shfl_xor_sync(0xffffffffu, s, off);
    s2 += __shfl_xor_sync(0xffffffffu, s2, off);
  }
  __shared__ float sb[16];
  if ((t & 31) == 0) { sb[t >> 5] = s; sb[(t >> 5) + 8] = s2; }
  __syncthreads();
  float tot = 0.f, tot2 = 0.f;
#pragma unroll
  for (int i = 0; i < 8; i++) { tot += sb[i]; tot2 += sb[i + 8]; }
  const float mean = tot * (1.f / D_);
  const float var  = tot2 * (1.f / D_) - mean * mean;
  const float inv  = rsqrtf(var + EPS_);
  float4 gm = ((const float4*)gamma)[t];
  float4 bb = ((const float4*)beta)[t];
  float4 o;
  o.x = (v.x - mean) * inv * gm.x + bb.x;
  o.y = (v.y - mean) * inv * gm.y + bb.y;
  o.z = (v.z - mean) * inv * gm.z + bb.z;
  o.w = (v.w - mean) * inv * gm.w + bb.w;
  ((float4*)(out + row * D_))[t] = o;
}

// ============================================================
// Flash attention with tensor cores (unscaled softmax), fused residual.
// Block: 64 queries x (head, batch). 256 threads = 8 warps (2 x 4).
// Phase A (scores 64x64): warp tile 32x16.
// Phase B (O += P V, 64x128): warp tile 32x32.
// ============================================================
#define QT 64
#define KTT 64
#define LQ 132
#define LK 132
#define LV 136
#define LP 68
#define ATTN_SMEM ((64 * (LQ + LK + LV + LP) + 128) * 4)

__global__ void __launch_bounds__(256) k_attn(const float* __restrict__ Qg,
                                              const float* __restrict__ Kg,
                                              const float* __restrict__ Vg,
                                              const float* __restrict__ modin,
                                              float* __restrict__ modout) {
  extern __shared__ float sm[];
  float* q_s = sm;
  float* k_s = q_s + 64 * LQ;
  float* v_s = k_s + 64 * LK;
  float* p_s = v_s + 64 * LV;
  float* alpha_s = p_s + 64 * LP;
  float* l_s = alpha_s + 64;

  const int t = threadIdx.x;
  const int lane = t & 31, wid = t >> 5;
  const int g = lane >> 2, tg = lane & 3;
  const int wr = wid >> 2, wc = wid & 3;

  const int q0 = blockIdx.x * QT;
  const int h = blockIdx.y, b = blockIdx.z;
  const size_t bh = (size_t)b * H_ + h;

  // load Q tile (converted to tf32)
  {
    const float* Qp = Qg + (bh * S_ + q0) * E_;
    const int col = (t & 31) * 4, row = t >> 5;
#pragma unroll
    for (int i = 0; i < 8; i++) {
      int r = row + i * 8;
      float4 v = *(const float4*)(Qp + (size_t)r * E_ + col);
      float4 w = make_float4(f2tf(v.x), f2tf(v.y), f2tf(v.z), f2tf(v.w));
      *(float4*)&q_s[r * LQ + col] = w;
    }
  }

  float o[2][4][4];
#pragma unroll
  for (int i = 0; i < 2; i++)
#pragma unroll
    for (int j = 0; j < 4; j++)
#pragma unroll
      for (int r = 0; r < 4; r++) o[i][j][r] = 0.f;

  float m_r = -1e30f, l_r = 0.f;  // valid for t < 64

  const float* Kp = Kg + bh * S_ * E_;
  const float* Vp = Vg + bh * S_ * E_;

  for (int kt = 0; kt < S_ / KTT; kt++) {
    if (kt) __syncthreads();  // protect smem reuse from previous phase B
    {
      const int col = (t & 31) * 4, row = t >> 5;
      const float* kb = Kp + (size_t)kt * KTT * E_;
      const float* vb = Vp + (size_t)kt * KTT * E_;
#pragma unroll
      for (int i = 0; i < 8; i++) {
        int r = row + i * 8;
        float4 kv = *(const float4*)(kb + (size_t)r * E_ + col);
        float4 vv = *(const float4*)(vb + (size_t)r * E_ + col);
        *(float4*)&k_s[r * LK + col] =
            make_float4(f2tf(kv.x), f2tf(kv.y), f2tf(kv.z), f2tf(kv.w));
        *(float4*)&v_s[r * LV + col] =
            make_float4(f2tf(vv.x), f2tf(vv.y), f2tf(vv.z), f2tf(vv.w));
      }
    }
    __syncthreads();

    // ---- phase A: scores = Q K^T (64x64), warp tile 32x16 ----
    float sc[2][2][4];
#pragma unroll
    for (int i = 0; i < 2; i++)
#pragma unroll
      for (int j = 0; j < 2; j++)
#pragma unroll
        for (int r = 0; r < 4; r++) sc[i][j][r] = 0.f;

    const uint32_t* qs = (const uint32_t*)q_s;
    const uint32_t* ks = (const uint32_t*)k_s;
#pragma unroll
    for (int kk = 0; kk < E_; kk += 8) {
      uint32_t af[2][4], bf[2][2];
#pragma unroll
      for (int i = 0; i < 2; i++) {
        int r0 = wr * 32 + i * 16;
        af[i][0] = qs[(r0 + g) * LQ + kk + tg];
        af[i][1] = qs[(r0 + g + 8) * LQ + kk + tg];
        af[i][2] = qs[(r0 + g) * LQ + kk + tg + 4];
        af[i][3] = qs[(r0 + g + 8) * LQ + kk + tg + 4];
      }
#pragma unroll
      for (int j = 0; j < 2; j++) {
        int c0 = wc * 16 + j * 8;
        bf[j][0] = ks[(c0 + g) * LK + kk + tg];
        bf[j][1] = ks[(c0 + g) * LK + kk + tg + 4];
      }
#pragma unroll
      for (int i = 0; i < 2; i++)
#pragma unroll
        for (int j = 0; j < 2; j++) mma_tf32(sc[i][j], af[i], bf[j]);
    }

    // scatter raw scores to p_s
#pragma unroll
    for (int i = 0; i < 2; i++) {
      int rA = wr * 32 + i * 16 + g;
#pragma unroll
      for (int j = 0; j < 2; j++) {
        int c = wc * 16 + j * 8 + 2 * tg;
        *(float2*)&p_s[rA * LP + c] = make_float2(sc[i][j][0], sc[i][j][1]);
        *(float2*)&p_s[(rA + 8) * LP + c] = make_float2(sc[i][j][2], sc[i][j][3]);
      }
    }
    __syncthreads();

    // ---- online softmax (one thread per row, t < 64) ----
    if (t < 64) {
      float4* pr = (float4*)&p_s[t * LP];
      float mt = -1e30f;
#pragma unroll
      for (int c = 0; c < 16; c++) {
        float4 v = pr[c];
        mt = fmaxf(mt, fmaxf(fmaxf(v.x, v.y), fmaxf(v.z, v.w)));
      }
      float mn = fmaxf(m_r, mt);
      float alpha = __expf(m_r - mn);
      m_r = mn;
      float s = 0.f;
#pragma unroll
      for (int c = 0; c < 16; c++) {
        float4 v = pr[c];
        v.x = __expf(v.x - mn); v.y = __expf(v.y - mn);
        v.z = __expf(v.z - mn); v.w = __expf(v.w - mn);
        s += v.x + v.y + v.z + v.w;
        pr[c] = make_float4(f2tf(v.x), f2tf(v.y), f2tf(v.z), f2tf(v.w));
      }
      l_r = l_r * alpha + s;
      alpha_s[t] = alpha;
      l_s[t] = l_r;
    }
    __syncthreads();

    // ---- rescale O accumulators ----
#pragma unroll
    for (int i = 0; i < 2; i++) {
      int rA = wr * 32 + i * 16 + g;
      float aA = alpha_s[rA], aB = alpha_s[rA + 8];
#pragma unroll
      for (int j = 0; j < 4; j++) {
        o[i][j][0] *= aA; o[i][j][1] *= aA;
        o[i][j][2] *= aB; o[i][j][3] *= aB;
      }
    }

    // ---- phase B: O += P V (64x128), warp tile 32x32 ----
    const uint32_t* ps = (const uint32_t*)p_s;
    const uint32_t* vs = (const uint32_t*)v_s;
#pragma unroll
    for (int kk = 0; kk < KTT; kk += 8) {
      uint32_t af[2][4], bf[4][2];
#pragma unroll
      for (int i = 0; i < 2; i++) {
        int r0 = wr * 32 + i * 16;
        af[i][0] = ps[(r0 + g) * LP + kk + tg];
        af[i][1] = ps[(r0 + g + 8) * LP + kk + tg];
        af[i][2] = ps[(r0 + g) * LP + kk + tg + 4];
        af[i][3] = ps[(r0 + g + 8) * LP + kk + tg + 4];
      }
#pragma unroll
      for (int j = 0; j < 4; j++) {
        int c0 = wc * 32 + j * 8;
        bf[j][0] = vs[(kk + tg) * LV + c0 + g];
        bf[j][1] = vs[(kk + tg + 4) * LV + c0 + g];
      }
#pragma unroll
      for (int i = 0; i < 2; i++)
#pragma unroll
        for (int j = 0; j < 4; j++) mma_tf32(o[i][j], af[i], bf[j]);
    }
  }

  // ---- epilogue: normalize + residual ----
#pragma unroll
  for (int i = 0; i < 2; i++) {
    int rA = wr * 32 + i * 16 + g;
    int rB = rA + 8;
    float invA = 1.f / l_s[rA];
    float invB = 1.f / l_s[rB];
#pragma unroll
    for (int j = 0; j < 4; j++) {
      int c = wc * 32 + j * 8 + 2 * tg;
      size_t baseA = ((size_t)b * S_ + q0 + rA) * D_ + (size_t)h * E_ + c;
      size_t baseB = ((size_t)b * S_ + q0 + rB) * D_ + (size_t)h * E_ + c;
      float2 mA = *(const float2*)(modin + baseA);
      float2 mB = *(const float2*)(modin + baseB);
      float2 oA = make_float2(mA.x + o[i][j][0] * invA, mA.y + o[i][j][1] * invA);
      float2 oB = make_float2(mB.x + o[i][j][2] * invB, mB.y + o[i][j][3] * invB);
      *(float2*)(modout + baseA) = oA;
      *(float2*)(modout + baseB) = oB;
    }
  }
}

// ============================================================
extern "C" void kernel_launch(void* const* d_in, const int* in_sizes, int n_in,
                              void* d_out, int out_size) {
  const float* x     = (const float*)d_in[0];
  const float* W_in  = (const float*)d_in[1];
  const float* gamma = (const float*)d_in[2];
  const float* beta  = (const float*)d_in[3];
  const float* Wq    = (const float*)d_in[4];
  const float* Wk    = (const float*)d_in[5];
  const float* Wv    = (const float*)d_in[6];
  const float* Wf    = (const float*)d_in[7];
  const float* bf    = (const float*)d_in[8];
  float* out = (float*)d_out;

  float *mod, *h, *q, *k, *v, *mod2, *h2;
  cudaGetSymbolAddress((void**)&mod,  g_mod);
  cudaGetSymbolAddress((void**)&h,    g_h);
  cudaGetSymbolAddress((void**)&q,    g_q);
  cudaGetSymbolAddress((void**)&k,    g_k);
  cudaGetSymbolAddress((void**)&v,    g_v);
  cudaGetSymbolAddress((void**)&mod2, g_mod2);
  cudaGetSymbolAddress((void**)&h2,   g_h2);

  cudaFuncSetAttribute(k_attn, cudaFuncAttributeMaxDynamicSharedMemorySize, ATTN_SMEM);

  dim3 gdense(D_ / GBN, NT_ / GBM);     // (8, 64)
  k_gemm_dense<<<gdense, 256>>>(x, W_in, mod);

  k_ln<<<NT_, 256>>>(mod, h, gamma, beta);

  dim3 ghead(S_ / GBM, B_ * H_);        // (16, 32)
  k_gemm_head<<<ghead, 256>>>(h, Wq, q);
  k_gemm_head<<<ghead, 256>>>(h, Wk, k);
  k_gemm_head<<<ghead, 256>>>(h, Wv, v);

  dim3 gattn(S_ / QT, H_, B_);          // (32, 8, 4)
  k_attn<<<gattn, 256, ATTN_SMEM>>>(q, k, v, mod, mod2);

  k_ln<<<NT_, 256>>>(mod2, h2, gamma, beta);

  k_gemm_ffn<<<gdense, 256>>>(h2, Wf, bf, mod2, out);
}